// round 14
// baseline (speedup 1.0000x reference)
#include <cuda_runtime.h>

#define NB   48
#define CHN  3
#define HH   256
#define WW   256
#define NIC  (NB*CHN)
#define NPIX (HH*WW)

#define TH   32
#define TW   64
#define PW   80              // plane stride (floats); rows 16B-aligned
#define PLANE (42*PW)        // one x or y halo plane (42 rows)
#define VP4  75              // Vb float4 stride: conflict-free LDS.128
#define NTHR 320
#define NTILE 32
#define NWORK (NTILE * NIC)  // 4608 tiles
#define GRID  296            // 2 blocks/SM * 148 SMs, all co-resident
#define NGRP  (NB * (HH/8))  // 1536 eight-row wbonus groups

// dynamic floats: 4 planes (x0,y0,x1,y1) + Vb; then wbuf (2*512 u32) + red
#define SM_BYTES ((4*PLANE + 4*TH*VP4)*4 + 2*2048 + 64)

__device__ double g_acc;
__device__ unsigned int g_count = 0;
__device__ volatile unsigned int g_bar = 0;
__device__ unsigned char g_wbonus[NB * NPIX];   // 3*m0 + 3*m1 + 2*m2 in [0,8]

// Normalized 1D Gaussian, k=11, sigma=1.5
__device__ constexpr float G[11] = {
    0.00102838f, 0.00759876f, 0.03600078f, 0.10936071f, 0.21300554f,
    0.26601172f,
    0.21300554f, 0.10936071f, 0.03600078f, 0.00759876f, 0.00102838f
};

__device__ __forceinline__ unsigned smem_addr(const void* p) {
    unsigned r;
    asm("{ .reg .u64 t; cvta.to.shared.u64 t, %1; cvt.u32.u64 %0, t; }"
        : "=r"(r) : "l"(p));
    return r;
}
__device__ __forceinline__ void cp_async16(unsigned dst, const void* src, unsigned sz) {
    asm volatile("cp.async.cg.shared.global [%0], [%1], 16, %2;"
                 :: "r"(dst), "l"(src), "r"(sz) : "memory");
}
__device__ __forceinline__ void cp_commit() {
    asm volatile("cp.async.commit_group;" ::: "memory");
}
__device__ __forceinline__ void cp_wait0() {
    asm volatile("cp.async.wait_group 0;" ::: "memory");
}

// ---------------------------------------------------------------------------
// ONE persistent kernel.
//  Pre-pass: all 296 blocks cooperatively rasterize g_wbonus (8-row groups,
//            crossing-threshold compaction), then global barrier.
//  Main:     R10 cp.async double-buffered tile pipeline (unchanged).
// ---------------------------------------------------------------------------
__global__ void __launch_bounds__(NTHR, 2) main_kernel(const float* __restrict__ pred,
                                                       const float* __restrict__ target,
                                                       const float* __restrict__ lmk,
                                                       float* __restrict__ out) {
    extern __shared__ float sm[];
    float*    VbF  = sm + 4*PLANE;
    float4*   Vb   = (float4*)VbF;                       // [TH][VP4]
    unsigned* wbuf = (unsigned*)(VbF + 4*TH*VP4);        // [2][512] words
    float*    red  = (float*)(wbuf + 1024);              // [10]

    // static scratch for the wmap pre-pass (separate from dynamic smem)
    __shared__ float wm_ethr[8][24];
    __shared__ int   wm_eflg[8][24];
    __shared__ float wm_cl[8][3][12];
    __shared__ int   wm_cc[8][3];
    __shared__ float wm_bxmin[3], wm_bxmax[3], wm_fymn[3], wm_fymx[3];
    __shared__ int   wm_pval[3];

    const int tid = threadIdx.x;
    const unsigned smbase = smem_addr(sm);

    // ================= Pre-pass: wbonus rasterization =================
    if (blockIdx.x == 0 && tid == 319) g_acc = 0.0;   // zero for this replay

    for (int grp = blockIdx.x; grp < NGRP; grp += GRID) {
        const int n     = grp >> 5;           // 32 groups per image
        const int rbase = (grp & 31) * 8;
        const float* L  = lmk + n * 136;

        if (tid < 192) {
            int rr = tid / 24, e = tid % 24;
            float Y = (float)(rbase + rr);
            int p    = (e < 6) ? 0 : ((e < 12) ? 1 : 2);
            int base = (p == 0) ? 36 : ((p == 1) ? 42 : 48);
            int cnt  = (p == 2) ? 12 : 6;
            int i    = e - ((p == 0) ? 0 : ((p == 1) ? 6 : 12));
            int j    = (i + 1 == cnt) ? 0 : i + 1;
            float x1 = L[2*(base+i)], y1 = L[2*(base+i)+1];
            float x2 = L[2*(base+j)], y2 = L[2*(base+j)+1];
            wm_eflg[rr][e] = ((y1 > Y) != (y2 > Y)) ? 1 : 0;
            wm_ethr[rr][e] = (x2 - x1) * (Y - y1) / (y2 - y1 + 1e-6f) + x1;
        } else if (tid < 195) {
            int p    = tid - 192;
            int base = (p == 0) ? 36 : ((p == 1) ? 42 : 48);
            int cnt  = (p == 2) ? 12 : 6;
            float mnx = 1e30f, mxx = -1e30f, mny = 1e30f, mxy = -1e30f;
            for (int i = 0; i < cnt; i++) {
                float x = L[2*(base+i)], y = L[2*(base+i)+1];
                mnx = fminf(mnx, x); mxx = fmaxf(mxx, x);
                mny = fminf(mny, y); mxy = fmaxf(mxy, y);
            }
            float fxmin = floorf(mnx), fxmax = floorf(mxx);
            wm_fymn[p] = floorf(mny);  wm_fymx[p] = floorf(mxy);
            wm_pval[p] = ((fxmin >= 0.f) && (wm_fymn[p] >= 0.f) &&
                          (fxmax < (float)WW) && (wm_fymx[p] < (float)HH)) ? 1 : 0;
            wm_bxmin[p] = fxmin; wm_bxmax[p] = fxmax;
        }
        __syncthreads();

        if (tid < 24) {
            int rr = tid / 3, p = tid % 3;
            float Y = (float)(rbase + rr);
            int s  = (p == 0) ? 0 : ((p == 1) ? 6 : 12);
            int cn = (p == 2) ? 12 : 6;
            int c = 0;
            if (wm_pval[p] && (Y >= wm_fymn[p]) && (Y < wm_fymx[p])) {
                for (int i = 0; i < cn; i++)
                    if (wm_eflg[rr][s + i]) wm_cl[rr][p][c++] = wm_ethr[rr][s + i];
            }
            wm_cc[rr][p] = c;
        }
        __syncthreads();

        if (tid < 256) {
            unsigned char* dst = g_wbonus + n * NPIX + rbase * WW;
            float X = (float)tid;
            #pragma unroll
            for (int r = 0; r < 8; r++) {
                int c0 = wm_cc[r][0], c1 = wm_cc[r][1], c2 = wm_cc[r][2];
                int bonus = 0;
                if ((c0 | c1 | c2) != 0) {
                    int cnt = 0;
                    for (int i = 0; i < c0; i++) cnt += (X < wm_cl[r][0][i]) ? 1 : 0;
                    if ((cnt & 1) && (X >= wm_bxmin[0]) && (X < wm_bxmax[0])) bonus += 3;
                    cnt = 0;
                    for (int i = 0; i < c1; i++) cnt += (X < wm_cl[r][1][i]) ? 1 : 0;
                    if ((cnt & 1) && (X >= wm_bxmin[1]) && (X < wm_bxmax[1])) bonus += 3;
                    cnt = 0;
                    for (int i = 0; i < c2; i++) cnt += (X < wm_cl[r][2][i]) ? 1 : 0;
                    if ((cnt & 1) && (X >= wm_bxmin[2]) && (X < wm_bxmax[2])) bonus += 2;
                }
                dst[r * WW + tid] = (unsigned char)bonus;
            }
        }
        __syncthreads();
    }

    // ---- global barrier: all wbonus writes visible before any tile runs ----
    __threadfence();
    __syncthreads();
    if (tid == 0) {
        atomicAdd((unsigned int*)&g_bar, 1u);
        while (g_bar < GRID) __nanosleep(64);
    }
    __syncthreads();

    // ================= Main: R10 tile pipeline (unchanged) =================
    const int vrg  = tid / 74;                 // V: valid for tid < 296
    const int vcol = tid - 74 * vrg;
    const int hrow = tid & 31;                 // H
    const int hcg  = tid >> 5;

    float lsum = 0.f;

    #define ISSUE_INTERIOR(wn, b)                                              \
    {                                                                          \
        int tile_ = (wn) & (NTILE - 1);                                        \
        int ic_   = (wn) >> 5;                                                 \
        int h0_ = (tile_ >> 2) * TH, w0_ = (tile_ & 3) * TW;                   \
        int n_  = ic_ / CHN;                                                   \
        const float* xb_ = pred   + ic_ * NPIX;                                \
        const float* yb_ = target + ic_ * NPIX;                                \
        for (int i = tid; i < 1344; i += NTHR) {                               \
            int a_   = i / 672;                                                \
            int rem_ = i - a_ * 672;                                           \
            int r_ = rem_ >> 4, k_ = rem_ & 15;                                \
            int gh_ = h0_ - 5 + r_;                                            \
            unsigned sz_ = (gh_ >= 0 && gh_ < HH) ? 16u : 0u;                  \
            int ghc_ = gh_ < 0 ? 0 : (gh_ > 255 ? 255 : gh_);                  \
            const float* src_ = (a_ ? yb_ : xb_) + ghc_ * WW + w0_ + k_ * 4;   \
            unsigned dst_ = smbase +                                           \
                (unsigned)(((2*(b) + a_) * PLANE + r_ * PW + 8 + 4*k_) * 4);   \
            cp_async16(dst_, src_, sz_);                                       \
        }                                                                      \
        if (tid < 128) {                                                       \
            int r_ = tid >> 2, k_ = tid & 3;                                   \
            const unsigned char* src_ =                                        \
                g_wbonus + n_ * NPIX + (h0_ + r_) * WW + w0_ + k_ * 16;        \
            unsigned dst_ = smbase + (unsigned)((4*PLANE + 4*TH*VP4) * 4       \
                            + (b) * 2048 + r_ * 64 + k_ * 16);                 \
            cp_async16(dst_, src_, 16u);                                       \
        }                                                                      \
    }

    // ---- prologue: fill buffer 0 for first tile ----
    int p = 0;
    {
        int work0 = blockIdx.x;
        ISSUE_INTERIOR(work0, 0);
        cp_commit();
        int tile_ = work0 & (NTILE - 1), ic_ = work0 >> 5;
        int h0_ = (tile_ >> 2) * TH, w0_ = (tile_ & 3) * TW;
        const float* xb_ = pred + ic_ * NPIX;
        const float* yb_ = target + ic_ * NPIX;
        #pragma unroll
        for (int q = 0; q < 3; q++) {
            int i = tid + NTHR * q;
            if (i < 840) {
                int a_ = i / 420, rem_ = i - a_ * 420;
                int r_ = rem_ / 10, cc_ = rem_ - r_ * 10;
                int gcol = (cc_ < 5) ? (w0_ - 5 + cc_) : (w0_ + 59 + cc_);
                int gh_  = h0_ - 5 + r_;
                bool ok  = (gh_ >= 0 && gh_ < HH && gcol >= 0 && gcol < WW);
                float v = ok ? ((a_ ? yb_ : xb_)[gh_ * WW + gcol]) : 0.f;
                int lc = (cc_ < 5) ? (3 + cc_) : (67 + cc_);
                sm[a_ * PLANE + r_ * PW + lc] = v;
            }
        }
        cp_wait0();
        __syncthreads();
    }

    // ---- persistent tile loop ----
    for (int work = blockIdx.x; work < NWORK; work += GRID) {
        const int wn = work + GRID;
        const bool havenext = (wn < NWORK);

        // A: issue async prefetch of next tile interior + wbonus
        if (havenext) {
            ISSUE_INTERIOR(wn, p ^ 1);
            cp_commit();
        }

        // side-halo register prefetch for next tile
        float ph0 = 0.f, ph1 = 0.f, ph2 = 0.f;
        if (havenext) {
            int tile_ = wn & (NTILE - 1), ic_ = wn >> 5;
            int h0_ = (tile_ >> 2) * TH, w0_ = (tile_ & 3) * TW;
            const float* xb_ = pred + ic_ * NPIX;
            const float* yb_ = target + ic_ * NPIX;
            #pragma unroll
            for (int q = 0; q < 3; q++) {
                int i = tid + NTHR * q;
                if (i < 840) {
                    int a_ = i / 420, rem_ = i - a_ * 420;
                    int r_ = rem_ / 10, cc_ = rem_ - r_ * 10;
                    int gcol = (cc_ < 5) ? (w0_ - 5 + cc_) : (w0_ + 59 + cc_);
                    int gh_  = h0_ - 5 + r_;
                    bool ok  = (gh_ >= 0 && gh_ < HH && gcol >= 0 && gcol < WW);
                    float v = ok ? ((a_ ? yb_ : xb_)[gh_ * WW + gcol]) : 0.f;
                    if (q == 0) ph0 = v; else if (q == 1) ph1 = v; else ph2 = v;
                }
            }
        }

        const float* Xc = sm + (2 * p) * PLANE;
        const float* Yc = sm + (2 * p + 1) * PLANE;

        // D: L1 + weighted-L1 fold from staged interior + wbonus bytes
        {
            const unsigned* wcur = wbuf + (p ? 512 : 0);
            for (int w = tid; w < 512; w += NTHR) {
                unsigned b4 = wcur[w];
                int r = w >> 4, k = w & 15;
                int base = (r + 5) * PW + 8 + 4 * k;
                #pragma unroll
                for (int j = 0; j < 4; j++) {
                    float xv = Xc[base + j], yv = Yc[base + j];
                    float ad = fabsf(xv - yv);
                    float bb = (float)((b4 >> (8 * j)) & 255u);
                    lsum += (15.f + 5.f * bb) * ad;   // 10*ad + 5*(1+b)*ad
                }
            }
        }

        // E: vertical conv of 4 fields, 8-row blocking (296 threads)
        if (tid < 296) {
            float amx[8], amy[8], ass[8], axy[8];
            #pragma unroll
            for (int o = 0; o < 8; o++) { amx[o]=0.f; amy[o]=0.f; ass[o]=0.f; axy[o]=0.f; }
            #pragma unroll
            for (int k = 0; k < 18; k++) {
                int idx = (8 * vrg + k) * PW + 3 + vcol;
                float xv = Xc[idx], yv = Yc[idx];
                float ss = fmaf(xv, xv, yv * yv);
                float xy = xv * yv;
                #pragma unroll
                for (int o = 0; o < 8; o++) {
                    int t = k - o;
                    if (t >= 0 && t < 11) {
                        float gg = G[t];
                        amx[o] = fmaf(gg, xv, amx[o]);
                        amy[o] = fmaf(gg, yv, amy[o]);
                        ass[o] = fmaf(gg, ss, ass[o]);
                        axy[o] = fmaf(gg, xy, axy[o]);
                    }
                }
            }
            #pragma unroll
            for (int o = 0; o < 8; o++)
                Vb[(8 * vrg + o) * VP4 + vcol] =
                    make_float4(amx[o], amy[o], ass[o], axy[o]);   // STS.128
        }
        __syncthreads();

        // F: horizontal conv (LDS.128) + dssim (256 threads)
        if (tid < 256) {
            const float4* vrow = Vb + hrow * VP4 + hcg * 8;
            float4 a[8];
            #pragma unroll
            for (int o = 0; o < 8; o++) a[o] = make_float4(0.f, 0.f, 0.f, 0.f);
            #pragma unroll
            for (int k = 0; k < 18; k++) {
                float4 v = vrow[k];
                #pragma unroll
                for (int o = 0; o < 8; o++) {
                    int t = k - o;
                    if (t >= 0 && t < 11) {
                        float gg = G[t];
                        a[o].x = fmaf(gg, v.x, a[o].x);
                        a[o].y = fmaf(gg, v.y, a[o].y);
                        a[o].z = fmaf(gg, v.z, a[o].z);
                        a[o].w = fmaf(gg, v.w, a[o].w);
                    }
                }
            }
            const float C1 = 0.01f * 0.01f;
            const float C2 = 0.03f * 0.03f;
            #pragma unroll
            for (int o = 0; o < 8; o++) {
                float mux = a[o].x, muy = a[o].y;
                float sxy  = a[o].w - mux * muy;
                float ssum = a[o].z - mux * mux - muy * muy;   // sigma_x+sigma_y
                float num = (2.f * mux * muy + C1) * (2.f * sxy + C2);
                float den = (mux * mux + muy * muy + C1) * (ssum + C2);
                float ssim = num / (den + 1e-8f);
                lsum += 10.f * 0.5f * (1.f - ssim);
            }
        }

        // B: store side-halo prefetch registers into buffer p^1
        if (havenext) {
            #pragma unroll
            for (int q = 0; q < 3; q++) {
                int i = tid + NTHR * q;
                if (i < 840) {
                    int a_ = i / 420, rem_ = i - a_ * 420;
                    int r_ = rem_ / 10, cc_ = rem_ - r_ * 10;
                    int lc = (cc_ < 5) ? (3 + cc_) : (67 + cc_);
                    float v = (q == 0) ? ph0 : ((q == 1) ? ph1 : ph2);
                    sm[(2 * (p ^ 1) + a_) * PLANE + r_ * PW + lc] = v;
                }
            }
        }

        cp_wait0();
        __syncthreads();
        p ^= 1;
    }

    // ---- final reduce: shuffles -> partials -> one double atomic ----
    #pragma unroll
    for (int s = 16; s > 0; s >>= 1)
        lsum += __shfl_xor_sync(0xFFFFFFFFu, lsum, s);
    if ((tid & 31) == 0) red[tid >> 5] = lsum;
    __syncthreads();
    if (tid == 0) {
        float t = 0.f;
        #pragma unroll
        for (int i = 0; i < NTHR / 32; i++) t += red[i];
        atomicAdd(&g_acc, (double)t);
        __threadfence();
        unsigned int old = atomicAdd(&g_count, 1u);
        if (old == GRID - 1) {
            double v = atomicAdd(&g_acc, 0.0);   // all adds visible
            out[0] = (float)(v * (1.0 / (double)(NB * CHN * NPIX)));
            g_acc = 0.0;                          // reset for next replay
            g_bar = 0;
            __threadfence();
            g_count = 0;
        }
    }
    #undef ISSUE_INTERIOR
}

extern "C" void kernel_launch(void* const* d_in, const int* in_sizes, int n_in,
                              void* d_out, int out_size) {
    (void)in_sizes; (void)n_in; (void)out_size;
    const float* pred   = (const float*)d_in[0];
    const float* target = (const float*)d_in[1];
    const float* lmk    = (const float*)d_in[2];
    float* out = (float*)d_out;

    cudaFuncSetAttribute(main_kernel, cudaFuncAttributeMaxDynamicSharedMemorySize,
                         SM_BYTES);

    main_kernel<<<GRID, NTHR, SM_BYTES>>>(pred, target, lmk, out);
}

// round 15
// speedup vs baseline: 1.0758x; 1.0758x over previous
#include <cuda_runtime.h>

#define NB   48
#define CHN  3
#define HH   256
#define WW   256
#define NIC  (NB*CHN)
#define NPIX (HH*WW)

#define TH   32
#define TW   64
#define PW   80              // plane stride (floats); rows 16B-aligned
#define PLANE (42*PW)        // one x or y halo plane (42 rows)
#define VP4  75              // Vb float4 stride: conflict-free LDS.128
#define NTHR 384             // 12 warps; 2 blocks/SM -> 24 resident warps
#define NTILE 32
#define NWORK (NTILE * NIC)  // 4608 tiles
#define GRID  296            // 2 blocks/SM * 148 SMs, persistent

// floats: 4 planes (x0,y0,x1,y1) + Vb; then wbuf (2*512 u32) + red
#define SM_BYTES ((4*PLANE + 4*TH*VP4)*4 + 2*2048 + 64)

__device__ double g_acc;
__device__ unsigned int g_count = 0;
__device__ unsigned char g_wbonus[NB * NPIX];   // 3*m0 + 3*m1 + 2*m2 in [0,8]

// Normalized 1D Gaussian, k=11, sigma=1.5
__device__ constexpr float G[11] = {
    0.00102838f, 0.00759876f, 0.03600078f, 0.10936071f, 0.21300554f,
    0.26601172f,
    0.21300554f, 0.10936071f, 0.03600078f, 0.00759876f, 0.00102838f
};

__device__ __forceinline__ unsigned smem_addr(const void* p) {
    unsigned r;
    asm("{ .reg .u64 t; cvta.to.shared.u64 t, %1; cvt.u32.u64 %0, t; }"
        : "=r"(r) : "l"(p));
    return r;
}
__device__ __forceinline__ void cp_async16(unsigned dst, const void* src, unsigned sz) {
    asm volatile("cp.async.cg.shared.global [%0], [%1], 16, %2;"
                 :: "r"(dst), "l"(src), "r"(sz) : "memory");
}
__device__ __forceinline__ void cp_commit() {
    asm volatile("cp.async.commit_group;" ::: "memory");
}
__device__ __forceinline__ void cp_wait0() {
    asm volatile("cp.async.wait_group 0;" ::: "memory");
}

// 8 rows per block; crossing-threshold compaction (proven R8/R10 version).
__global__ void __launch_bounds__(WW) wmap_kernel(const float* __restrict__ lmk) {
    const int rbase = blockIdx.x * 8;
    const int n     = blockIdx.y;
    const int tid   = threadIdx.x;

    __shared__ float ethr[8][24];
    __shared__ int   eflg[8][24];
    __shared__ float clist[8][3][12];
    __shared__ int   ccnt[8][3];
    __shared__ float bxmin[3], bxmax[3], fymn[3], fymx[3];
    __shared__ int   pval[3];

    if (rbase == 0 && n == 0 && tid == 255) g_acc = 0.0;  // zero per replay

    const float* L = lmk + n * 136;

    if (tid < 192) {
        int rr = tid / 24, e = tid % 24;
        float Y = (float)(rbase + rr);
        int p    = (e < 6) ? 0 : ((e < 12) ? 1 : 2);
        int base = (p == 0) ? 36 : ((p == 1) ? 42 : 48);
        int cnt  = (p == 2) ? 12 : 6;
        int i    = e - ((p == 0) ? 0 : ((p == 1) ? 6 : 12));
        int j    = (i + 1 == cnt) ? 0 : i + 1;
        float x1 = L[2*(base+i)], y1 = L[2*(base+i)+1];
        float x2 = L[2*(base+j)], y2 = L[2*(base+j)+1];
        eflg[rr][e] = ((y1 > Y) != (y2 > Y)) ? 1 : 0;
        ethr[rr][e] = (x2 - x1) * (Y - y1) / (y2 - y1 + 1e-6f) + x1;
    } else if (tid < 195) {
        int p    = tid - 192;
        int base = (p == 0) ? 36 : ((p == 1) ? 42 : 48);
        int cnt  = (p == 2) ? 12 : 6;
        float mnx = 1e30f, mxx = -1e30f, mny = 1e30f, mxy = -1e30f;
        for (int i = 0; i < cnt; i++) {
            float x = L[2*(base+i)], y = L[2*(base+i)+1];
            mnx = fminf(mnx, x); mxx = fmaxf(mxx, x);
            mny = fminf(mny, y); mxy = fmaxf(mxy, y);
        }
        float fxmin = floorf(mnx), fxmax = floorf(mxx);
        fymn[p] = floorf(mny);  fymx[p] = floorf(mxy);
        pval[p] = ((fxmin >= 0.f) && (fymn[p] >= 0.f) &&
                   (fxmax < (float)WW) && (fymx[p] < (float)HH)) ? 1 : 0;
        bxmin[p] = fxmin; bxmax[p] = fxmax;
    }
    __syncthreads();

    if (tid < 24) {
        int rr = tid / 3, p = tid % 3;
        float Y = (float)(rbase + rr);
        int s  = (p == 0) ? 0 : ((p == 1) ? 6 : 12);
        int cn = (p == 2) ? 12 : 6;
        int c = 0;
        if (pval[p] && (Y >= fymn[p]) && (Y < fymx[p])) {
            for (int i = 0; i < cn; i++)
                if (eflg[rr][s + i]) clist[rr][p][c++] = ethr[rr][s + i];
        }
        ccnt[rr][p] = c;
    }
    __syncthreads();

    unsigned char* dst = g_wbonus + n * NPIX + rbase * WW;
    float X = (float)tid;
    #pragma unroll
    for (int r = 0; r < 8; r++) {
        int c0 = ccnt[r][0], c1 = ccnt[r][1], c2 = ccnt[r][2];
        int bonus = 0;
        if ((c0 | c1 | c2) != 0) {
            int cnt = 0;
            for (int i = 0; i < c0; i++) cnt += (X < clist[r][0][i]) ? 1 : 0;
            if ((cnt & 1) && (X >= bxmin[0]) && (X < bxmax[0])) bonus += 3;
            cnt = 0;
            for (int i = 0; i < c1; i++) cnt += (X < clist[r][1][i]) ? 1 : 0;
            if ((cnt & 1) && (X >= bxmin[1]) && (X < bxmax[1])) bonus += 3;
            cnt = 0;
            for (int i = 0; i < c2; i++) cnt += (X < clist[r][2][i]) ? 1 : 0;
            if ((cnt & 1) && (X >= bxmin[2]) && (X < bxmax[2])) bonus += 2;
        }
        dst[r * WW + tid] = (unsigned char)bonus;
    }
}

// ---------------------------------------------------------------------------
// Persistent fused main: R10 structure, 384 threads (24 resident warps/SM).
// ---------------------------------------------------------------------------
__global__ void __launch_bounds__(NTHR, 2) main_kernel(const float* __restrict__ pred,
                                                       const float* __restrict__ target,
                                                       float* __restrict__ out) {
    extern __shared__ float sm[];
    float*    VbF  = sm + 4*PLANE;
    float4*   Vb   = (float4*)VbF;                       // [TH][VP4]
    unsigned* wbuf = (unsigned*)(VbF + 4*TH*VP4);        // [2][512] words
    float*    red  = (float*)(wbuf + 1024);              // [16]

    const int tid = threadIdx.x;
    const unsigned smbase = smem_addr(sm);

    const int vrg  = tid / 74;                 // V: valid for tid < 296
    const int vcol = tid - 74 * vrg;
    const int hrow = tid & 31;                 // H: valid for tid < 256
    const int hcg  = tid >> 5;

    float lsum = 0.f;

    #define ISSUE_INTERIOR(wn, b)                                              \
    {                                                                          \
        int tile_ = (wn) & (NTILE - 1);                                        \
        int ic_   = (wn) >> 5;                                                 \
        int h0_ = (tile_ >> 2) * TH, w0_ = (tile_ & 3) * TW;                   \
        int n_  = ic_ / CHN;                                                   \
        const float* xb_ = pred   + ic_ * NPIX;                                \
        const float* yb_ = target + ic_ * NPIX;                                \
        for (int i = tid; i < 1344; i += NTHR) {                               \
            int a_   = i / 672;                                                \
            int rem_ = i - a_ * 672;                                           \
            int r_ = rem_ >> 4, k_ = rem_ & 15;                                \
            int gh_ = h0_ - 5 + r_;                                            \
            unsigned sz_ = (gh_ >= 0 && gh_ < HH) ? 16u : 0u;                  \
            int ghc_ = gh_ < 0 ? 0 : (gh_ > 255 ? 255 : gh_);                  \
            const float* src_ = (a_ ? yb_ : xb_) + ghc_ * WW + w0_ + k_ * 4;   \
            unsigned dst_ = smbase +                                           \
                (unsigned)(((2*(b) + a_) * PLANE + r_ * PW + 8 + 4*k_) * 4);   \
            cp_async16(dst_, src_, sz_);                                       \
        }                                                                      \
        if (tid < 128) {                                                       \
            int r_ = tid >> 2, k_ = tid & 3;                                   \
            const unsigned char* src_ =                                        \
                g_wbonus + n_ * NPIX + (h0_ + r_) * WW + w0_ + k_ * 16;        \
            unsigned dst_ = smbase + (unsigned)((4*PLANE + 4*TH*VP4) * 4       \
                            + (b) * 2048 + r_ * 64 + k_ * 16);                 \
            cp_async16(dst_, src_, 16u);                                       \
        }                                                                      \
    }

    // ---- prologue: fill buffer 0 for first tile ----
    int p = 0;
    {
        int work0 = blockIdx.x;
        ISSUE_INTERIOR(work0, 0);
        cp_commit();
        int tile_ = work0 & (NTILE - 1), ic_ = work0 >> 5;
        int h0_ = (tile_ >> 2) * TH, w0_ = (tile_ & 3) * TW;
        const float* xb_ = pred + ic_ * NPIX;
        const float* yb_ = target + ic_ * NPIX;
        #pragma unroll
        for (int q = 0; q < 3; q++) {
            int i = tid + NTHR * q;
            if (i < 840) {
                int a_ = i / 420, rem_ = i - a_ * 420;
                int r_ = rem_ / 10, cc_ = rem_ - r_ * 10;
                int gcol = (cc_ < 5) ? (w0_ - 5 + cc_) : (w0_ + 59 + cc_);
                int gh_  = h0_ - 5 + r_;
                bool ok  = (gh_ >= 0 && gh_ < HH && gcol >= 0 && gcol < WW);
                float v = ok ? ((a_ ? yb_ : xb_)[gh_ * WW + gcol]) : 0.f;
                int lc = (cc_ < 5) ? (3 + cc_) : (67 + cc_);
                sm[a_ * PLANE + r_ * PW + lc] = v;
            }
        }
        cp_wait0();
        __syncthreads();
    }

    // ---- persistent tile loop ----
    for (int work = blockIdx.x; work < NWORK; work += GRID) {
        const int wn = work + GRID;
        const bool havenext = (wn < NWORK);

        // A: issue async prefetch of next tile interior + wbonus
        if (havenext) {
            ISSUE_INTERIOR(wn, p ^ 1);
            cp_commit();
        }

        // side-halo register prefetch for next tile
        float ph0 = 0.f, ph1 = 0.f, ph2 = 0.f;
        if (havenext) {
            int tile_ = wn & (NTILE - 1), ic_ = wn >> 5;
            int h0_ = (tile_ >> 2) * TH, w0_ = (tile_ & 3) * TW;
            const float* xb_ = pred + ic_ * NPIX;
            const float* yb_ = target + ic_ * NPIX;
            #pragma unroll
            for (int q = 0; q < 3; q++) {
                int i = tid + NTHR * q;
                if (i < 840) {
                    int a_ = i / 420, rem_ = i - a_ * 420;
                    int r_ = rem_ / 10, cc_ = rem_ - r_ * 10;
                    int gcol = (cc_ < 5) ? (w0_ - 5 + cc_) : (w0_ + 59 + cc_);
                    int gh_  = h0_ - 5 + r_;
                    bool ok  = (gh_ >= 0 && gh_ < HH && gcol >= 0 && gcol < WW);
                    float v = ok ? ((a_ ? yb_ : xb_)[gh_ * WW + gcol]) : 0.f;
                    if (q == 0) ph0 = v; else if (q == 1) ph1 = v; else ph2 = v;
                }
            }
        }

        const float* Xc = sm + (2 * p) * PLANE;
        const float* Yc = sm + (2 * p + 1) * PLANE;

        // D: L1 + weighted-L1 fold from staged interior + wbonus bytes
        {
            const unsigned* wcur = wbuf + (p ? 512 : 0);
            for (int w = tid; w < 512; w += NTHR) {
                unsigned b4 = wcur[w];
                int r = w >> 4, k = w & 15;
                int base = (r + 5) * PW + 8 + 4 * k;
                #pragma unroll
                for (int j = 0; j < 4; j++) {
                    float xv = Xc[base + j], yv = Yc[base + j];
                    float ad = fabsf(xv - yv);
                    float bb = (float)((b4 >> (8 * j)) & 255u);
                    lsum += (15.f + 5.f * bb) * ad;   // 10*ad + 5*(1+b)*ad
                }
            }
        }

        // E: vertical conv of 4 fields, 8-row blocking (296 threads)
        if (tid < 296) {
            float amx[8], amy[8], ass[8], axy[8];
            #pragma unroll
            for (int o = 0; o < 8; o++) { amx[o]=0.f; amy[o]=0.f; ass[o]=0.f; axy[o]=0.f; }
            #pragma unroll
            for (int k = 0; k < 18; k++) {
                int idx = (8 * vrg + k) * PW + 3 + vcol;
                float xv = Xc[idx], yv = Yc[idx];
                float ss = fmaf(xv, xv, yv * yv);
                float xy = xv * yv;
                #pragma unroll
                for (int o = 0; o < 8; o++) {
                    int t = k - o;
                    if (t >= 0 && t < 11) {
                        float gg = G[t];
                        amx[o] = fmaf(gg, xv, amx[o]);
                        amy[o] = fmaf(gg, yv, amy[o]);
                        ass[o] = fmaf(gg, ss, ass[o]);
                        axy[o] = fmaf(gg, xy, axy[o]);
                    }
                }
            }
            #pragma unroll
            for (int o = 0; o < 8; o++)
                Vb[(8 * vrg + o) * VP4 + vcol] =
                    make_float4(amx[o], amy[o], ass[o], axy[o]);   // STS.128
        }
        __syncthreads();

        // F: horizontal conv (LDS.128) + dssim (256 threads)
        if (tid < 256) {
            const float4* vrow = Vb + hrow * VP4 + hcg * 8;
            float4 a[8];
            #pragma unroll
            for (int o = 0; o < 8; o++) a[o] = make_float4(0.f, 0.f, 0.f, 0.f);
            #pragma unroll
            for (int k = 0; k < 18; k++) {
                float4 v = vrow[k];
                #pragma unroll
                for (int o = 0; o < 8; o++) {
                    int t = k - o;
                    if (t >= 0 && t < 11) {
                        float gg = G[t];
                        a[o].x = fmaf(gg, v.x, a[o].x);
                        a[o].y = fmaf(gg, v.y, a[o].y);
                        a[o].z = fmaf(gg, v.z, a[o].z);
                        a[o].w = fmaf(gg, v.w, a[o].w);
                    }
                }
            }
            const float C1 = 0.01f * 0.01f;
            const float C2 = 0.03f * 0.03f;
            #pragma unroll
            for (int o = 0; o < 8; o++) {
                float mux = a[o].x, muy = a[o].y;
                float sxy  = a[o].w - mux * muy;
                float ssum = a[o].z - mux * mux - muy * muy;   // sigma_x+sigma_y
                float num = (2.f * mux * muy + C1) * (2.f * sxy + C2);
                float den = (mux * mux + muy * muy + C1) * (ssum + C2);
                float ssim = num / (den + 1e-8f);
                lsum += 10.f * 0.5f * (1.f - ssim);
            }
        }

        // B: store side-halo prefetch registers into buffer p^1
        if (havenext) {
            #pragma unroll
            for (int q = 0; q < 3; q++) {
                int i = tid + NTHR * q;
                if (i < 840) {
                    int a_ = i / 420, rem_ = i - a_ * 420;
                    int r_ = rem_ / 10, cc_ = rem_ - r_ * 10;
                    int lc = (cc_ < 5) ? (3 + cc_) : (67 + cc_);
                    float v = (q == 0) ? ph0 : ((q == 1) ? ph1 : ph2);
                    sm[(2 * (p ^ 1) + a_) * PLANE + r_ * PW + lc] = v;
                }
            }
        }

        cp_wait0();
        __syncthreads();
        p ^= 1;
    }

    // ---- final reduce: shuffles -> partials -> one double atomic ----
    #pragma unroll
    for (int s = 16; s > 0; s >>= 1)
        lsum += __shfl_xor_sync(0xFFFFFFFFu, lsum, s);
    if ((tid & 31) == 0) red[tid >> 5] = lsum;
    __syncthreads();
    if (tid == 0) {
        float t = 0.f;
        #pragma unroll
        for (int i = 0; i < NTHR / 32; i++) t += red[i];
        atomicAdd(&g_acc, (double)t);
        __threadfence();
        unsigned int old = atomicAdd(&g_count, 1u);
        if (old == GRID - 1) {
            double v = atomicAdd(&g_acc, 0.0);   // coherent read of final sum
            out[0] = (float)(v * (1.0 / (double)(NB * CHN * NPIX)));
            g_count = 0;                          // reset for next graph replay
        }
    }
    #undef ISSUE_INTERIOR
}

extern "C" void kernel_launch(void* const* d_in, const int* in_sizes, int n_in,
                              void* d_out, int out_size) {
    (void)in_sizes; (void)n_in; (void)out_size;
    const float* pred   = (const float*)d_in[0];
    const float* target = (const float*)d_in[1];
    const float* lmk    = (const float*)d_in[2];
    float* out = (float*)d_out;

    cudaFuncSetAttribute(main_kernel, cudaFuncAttributeMaxDynamicSharedMemorySize,
                         SM_BYTES);

    wmap_kernel<<<dim3(HH / 8, NB), WW>>>(lmk);
    main_kernel<<<GRID, NTHR, SM_BYTES>>>(pred, target, out);
}